// round 12
// baseline (speedup 1.0000x reference)
#include <cuda_runtime.h>
#include <mma.h>
#include <cuda_bf16.h>
#include <math.h>
#include <stdint.h>

using namespace nvcuda;

#define B_    2
#define S_    2048
#define NH_   16
#define HD_   128
#define NC_   32
#define QKVW  6144
#define NHD   2048

__device__ float g_qkv[(size_t)B_ * S_ * QKVW];
__device__ float g_kv[(size_t)B_ * NH_ * NC_ * HD_ * HD_];
__device__ float g_state[(size_t)B_ * NH_ * NC_ * HD_ * HD_];
__device__ float g_o[(size_t)B_ * S_ * NHD];
__device__ float g_gate[(size_t)B_ * S_ * NHD];
__device__ __nv_bfloat16 g_a2[16777216];   // A [4096, 4096] = [Ah | Al]
__device__ __nv_bfloat16 g_w2[41943040];   // fused [4096,8192]=[Bh;Bl] qkv|g, then dense [4096,2048]

__device__ __forceinline__ float slope_for(int h) {
    return -exp2f(-0.5f * (float)(h + 1)) * (1.0f + 1e-5f);
}
__device__ __forceinline__ uint32_t smem_u32(const void* p) {
    uint32_t a;
    asm("{ .reg .u64 t; cvta.to.shared.u64 t, %1; cvt.u32.u64 %0, t; }" : "=r"(a) : "l"(p));
    return a;
}
__device__ __forceinline__ void cp_async16(uint32_t sa, const void* ga) {
    asm volatile("cp.async.cg.shared.global [%0], [%1], 16;" :: "r"(sa), "l"(ga));
}
__device__ __forceinline__ void split2(float x, __nv_bfloat16& h, __nv_bfloat16& l) {
    h = __float2bfloat16(x);
    l = __float2bfloat16(x - __bfloat162float(h));
}

// ---------- split A [M,K] fp32 -> [M,2K] bf16 as (Ah | Al) ----------
__global__ void split_A2(const float* __restrict__ in, __nv_bfloat16* __restrict__ out, int K) {
    size_t idx = ((size_t)blockIdx.x * 256 + threadIdx.x) * 4;
    int m = (int)(idx / K), k = (int)(idx % K);
    float4 v = *(const float4*)(in + idx);
    __nv_bfloat16 h[4], l[4];
    split2(v.x, h[0], l[0]); split2(v.y, h[1], l[1]);
    split2(v.z, h[2], l[2]); split2(v.w, h[3], l[3]);
    __nv_bfloat16* o = out + (size_t)m * 2 * K;
    *(uint2*)(o + k)     = *(const uint2*)h;
    *(uint2*)(o + K + k) = *(const uint2*)l;
}

// ---------- split B [K,N] fp32 -> rows (Bh ; Bl) ----------
__global__ void split_B2(const float* __restrict__ in, __nv_bfloat16* __restrict__ out,
                         int K, int N, int ldo, int col_off) {
    size_t idx = ((size_t)blockIdx.x * 256 + threadIdx.x) * 4;
    int k = (int)(idx / N), n = (int)(idx % N);
    float4 v = *(const float4*)(in + idx);
    __nv_bfloat16 h[4], l[4];
    split2(v.x, h[0], l[0]); split2(v.y, h[1], l[1]);
    split2(v.z, h[2], l[2]); split2(v.w, h[3], l[3]);
    *(uint2*)(out + (size_t)k * ldo + col_off + n)       = *(const uint2*)h;
    *(uint2*)(out + (size_t)(K + k) * ldo + col_off + n) = *(const uint2*)l;
}

// ---------- bf16 split-GEMM, dual output, 4 warps/SMSP ----------
// CTA 128x128, 256 threads = 8 warps (2 row x 4 col), warp tile 64x32.
// 3-stage ring, single barrier per K-tile, 2 CTAs/SM (<=128 regs/thread).
// Logical K' = 96 tiles: 0-31 Ah@Bh, 32-63 Al@Bh, 64-95 Ah@Bl.
#define AS_LD 72
#define BS_LD 136
#define STG_H (128 * AS_LD + 64 * BS_LD)   // 17920 halves / stage

typedef wmma::fragment<wmma::matrix_a, 16, 16, 16, __nv_bfloat16, wmma::row_major> FragA;
typedef wmma::fragment<wmma::matrix_b, 16, 16, 16, __nv_bfloat16, wmma::row_major> FragB;

__global__ void __launch_bounds__(256, 2)
gemm_bf16(const __nv_bfloat16* __restrict__ A, const __nv_bfloat16* __restrict__ Bm,
          float* __restrict__ C1, float* __restrict__ C2,
          int M, int N1, int N2, int ldb)
{
    extern __shared__ __nv_bfloat16 smh[];

    const int tid = threadIdx.x, warp = tid >> 5;
    const int wr = warp >> 2, wc = warp & 3;       // 2 x 4 warp grid
    const int bm = blockIdx.y * 128, bn = blockIdx.x * 128;

    __nv_bfloat16* pA[3];
    __nv_bfloat16* pB[3];
    uint32_t uA[3], uB[3];
#pragma unroll
    for (int s = 0; s < 3; s++) {
        pA[s] = smh + s * STG_H;
        pB[s] = pA[s] + 128 * AS_LD;
        uA[s] = smem_u32(pA[s]);
        uB[s] = smem_u32(pB[s]);
    }

    wmma::fragment<wmma::accumulator, 16, 16, 16, float> acc[4][2];
#pragma unroll
    for (int i = 0; i < 4; i++)
#pragma unroll
        for (int j = 0; j < 2; j++) wmma::fill_fragment(acc[i][j], 0.0f);

    auto load_stage = [&](int s, int i) {
        const int kA = ((i < 64) ? i : i - 64) << 6;
        const int kB = ((i < 32) ? i : i - 32) << 6;
#pragma unroll
        for (int j = 0; j < 4; j++) {            // A: 128 rows x 64 halves (1024 x 16B)
            int id = tid + j * 256;
            int r = id >> 3, c = (id & 7) << 3;
            cp_async16(uA[s] + (uint32_t)(r * AS_LD + c) * 2u,
                       A + (size_t)(bm + r) * 4096 + kA + c);
        }
#pragma unroll
        for (int j = 0; j < 4; j++) {            // B: 64 rows x 128 halves (1024 x 16B)
            int id = tid + j * 256;
            int r = id >> 4, c = (id & 15) << 3;
            cp_async16(uB[s] + (uint32_t)(r * BS_LD + c) * 2u,
                       Bm + (size_t)(kB + r) * ldb + bn + c);
        }
        asm volatile("cp.async.commit_group;" ::: "memory");
    };

    const int nk = 96;
    load_stage(0, 0);
    load_stage(1, 1);

    for (int i = 0; i < nk; i++) {
        const int s = i % 3;
        if (i < nk - 1) {
            asm volatile("cp.async.wait_group 1;" ::: "memory");
        } else {
            asm volatile("cp.async.wait_group 0;" ::: "memory");
        }
        __syncthreads();                       // also retires reads of stage (i-1)%3
        if (i + 2 < nk) load_stage((i + 2) % 3, i + 2);

        const __nv_bfloat16* a0 = pA[s] + wr * 64 * AS_LD;
        const __nv_bfloat16* b0 = pB[s] + wc * 32;
#pragma unroll
        for (int kk = 0; kk < 64; kk += 16) {
            FragA af[4];
            FragB bf[2];
#pragma unroll
            for (int x = 0; x < 4; x++)
                wmma::load_matrix_sync(af[x], a0 + x * 16 * AS_LD + kk, AS_LD);
#pragma unroll
            for (int y = 0; y < 2; y++)
                wmma::load_matrix_sync(bf[y], b0 + kk * BS_LD + y * 16, BS_LD);
#pragma unroll
            for (int x = 0; x < 4; x++)
#pragma unroll
                for (int y = 0; y < 2; y++)
                    wmma::mma_sync(acc[x][y], af[x], bf[y], acc[x][y]);
        }
    }

    if (bn < N1) {
#pragma unroll
        for (int x = 0; x < 4; x++)
#pragma unroll
            for (int y = 0; y < 2; y++)
                wmma::store_matrix_sync(C1 + (size_t)(bm + wr * 64 + x * 16) * N1 + bn + wc * 32 + y * 16,
                                        acc[x][y], N1, wmma::mem_row_major);
    } else {
        const int bn2 = bn - N1;
#pragma unroll
        for (int x = 0; x < 4; x++)
#pragma unroll
            for (int y = 0; y < 2; y++)
                wmma::store_matrix_sync(C2 + (size_t)(bm + wr * 64 + x * 16) * N2 + bn2 + wc * 32 + y * 16,
                                        acc[x][y], N2, wmma::mem_row_major);
    }
}

// ======= fused per-row RMSNorm + partial RoPE on a 64x129 smem tile ==========
__device__ __forceinline__ void norm_rope_tile(float* st, const float* __restrict__ w,
                                               const int* __restrict__ positions,
                                               int c, int tid, float row_extra_scale_slope,
                                               bool apply_extra)
{
    const int r = tid >> 2, t4 = tid & 3;
    float ss = 0.0f;
#pragma unroll 8
    for (int d = t4 * 32; d < t4 * 32 + 32; d++) {
        float a = st[r * 129 + d];
        ss += a * a;
    }
    ss += __shfl_xor_sync(0xffffffffu, ss, 1);
    ss += __shfl_xor_sync(0xffffffffu, ss, 2);
    float f = rsqrtf(ss * (1.0f / 128.0f) + 1e-6f);
    if (apply_extra) f *= expf(row_extra_scale_slope * (float)(r + 1));
#pragma unroll 8
    for (int d = t4 * 32; d < t4 * 32 + 32; d++)
        st[r * 129 + d] *= f * w[d];
    __syncthreads();
    for (int p = tid; p < 64 * 32; p += 256) {
        int rr = p >> 5, j = p & 31;
        float pos = (float)positions[c * 64 + rr];
        float inv = exp2f(-(float)j * (13.287712379549449f / 32.0f));
        float ang = pos * inv;
        float cs = cosf(ang), sn = sinf(ang);
        float x1 = st[rr * 129 + j], x2 = st[rr * 129 + j + 32];
        st[rr * 129 + j]      = x1 * cs - x2 * sn;
        st[rr * 129 + j + 32] = x2 * cs + x1 * sn;
    }
    __syncthreads();
}

// ---------- per-chunk intra output + KV outer product (norm+rope fused) -------
__global__ void __launch_bounds__(256, 2) chunk_stats_kernel(
    const float* __restrict__ qnw, const float* __restrict__ knw,
    const int* __restrict__ positions)
{
    extern __shared__ float sm[];
    float* sK   = sm;
    float* sQV  = sm + 64 * 129;
    float* sS   = sm + 2 * 64 * 129;
    float* sdec = sS + 64 * 65;

    const int bhc = blockIdx.x;
    const int c = bhc & 31, h = (bhc >> 5) & 15, b = bhc >> 9;
    const int tid = threadIdx.x;
    const float slope = slope_for(h);
    const int ty = tid >> 4, tx = tid & 15;

    const size_t rowbase = ((size_t)(b * S_) + c * 64) * QKVW + h * HD_;

    for (int f = tid; f < 2048; f += 256) {
        int i = f >> 5, d4 = (f & 31) << 2;
        const float* gp = g_qkv + rowbase + (size_t)i * QKVW + d4;
        float4 q = *(const float4*)(gp);
        float4 k = *(const float4*)(gp + 2048);
        sQV[i * 129 + d4 + 0] = q.x; sQV[i * 129 + d4 + 1] = q.y;
        sQV[i * 129 + d4 + 2] = q.z; sQV[i * 129 + d4 + 3] = q.w;
        sK[i * 129 + d4 + 0] = k.x;  sK[i * 129 + d4 + 1] = k.y;
        sK[i * 129 + d4 + 2] = k.z;  sK[i * 129 + d4 + 3] = k.w;
    }
    if (tid < 64) sdec[tid] = expf(slope * (float)(63 - tid));
    __syncthreads();

    norm_rope_tile(sQV, qnw, positions, c, tid, 0.0f, false);
    norm_rope_tile(sK,  knw, positions, c, tid, 0.0f, false);

    {   // scores 4x4 per thread
        float a[4][4] = {};
        const int i0 = ty * 4, j0 = tx * 4;
        for (int d = 0; d < 128; d++) {
            float q[4], kk[4];
#pragma unroll
            for (int r = 0; r < 4; r++) q[r] = sQV[(i0 + r) * 129 + d];
#pragma unroll
            for (int cc = 0; cc < 4; cc++) kk[cc] = sK[(j0 + cc) * 129 + d];
#pragma unroll
            for (int r = 0; r < 4; r++)
#pragma unroll
                for (int cc = 0; cc < 4; cc++) a[r][cc] += q[r] * kk[cc];
        }
#pragma unroll
        for (int r = 0; r < 4; r++)
#pragma unroll
            for (int cc = 0; cc < 4; cc++) {
                int i = i0 + r, j = j0 + cc;
                sS[i * 65 + j] = (i >= j) ? a[r][cc] * expf(slope * (float)(i - j)) : 0.0f;
            }
    }
    __syncthreads();

    for (int f = tid; f < 2048; f += 256) {
        int i = f >> 5, d4 = (f & 31) << 2;
        float4 v = *(const float4*)(g_qkv + rowbase + (size_t)i * QKVW + 4096 + d4);
        sQV[i * 129 + d4 + 0] = v.x; sQV[i * 129 + d4 + 1] = v.y;
        sQV[i * 129 + d4 + 2] = v.z; sQV[i * 129 + d4 + 3] = v.w;
        float kd = sdec[i];
        sK[i * 129 + d4 + 0] *= kd; sK[i * 129 + d4 + 1] *= kd;
        sK[i * 129 + d4 + 2] *= kd; sK[i * 129 + d4 + 3] *= kd;
    }
    __syncthreads();

    const size_t obase = ((size_t)(b * S_) + c * 64) * NHD + h * HD_;
    {   // o_intra
        float a0[4][4] = {}, a1[4][4] = {};
        const int i0 = ty * 4, e0 = tx * 4;
        for (int j = 0; j < 64; j++) {
            float s[4], v0[4], v1[4];
#pragma unroll
            for (int r = 0; r < 4; r++) s[r] = sS[(i0 + r) * 65 + j];
#pragma unroll
            for (int cc = 0; cc < 4; cc++) {
                v0[cc] = sQV[j * 129 + e0 + cc];
                v1[cc] = sQV[j * 129 + e0 + 64 + cc];
            }
#pragma unroll
            for (int r = 0; r < 4; r++)
#pragma unroll
                for (int cc = 0; cc < 4; cc++) {
                    a0[r][cc] += s[r] * v0[cc];
                    a1[r][cc] += s[r] * v1[cc];
                }
        }
#pragma unroll
        for (int r = 0; r < 4; r++)
#pragma unroll
            for (int cc = 0; cc < 4; cc++) {
                g_o[obase + (size_t)(i0 + r) * NHD + e0 + cc]      = a0[r][cc];
                g_o[obase + (size_t)(i0 + r) * NHD + e0 + 64 + cc] = a1[r][cc];
            }
    }

    {   // KV
        float a0[8][4] = {}, a1[8][4] = {};
        const int d0 = ty * 8, e0 = tx * 4;
        for (int j = 0; j < 64; j++) {
            float kk[8], v0[4], v1[4];
#pragma unroll
            for (int r = 0; r < 8; r++) kk[r] = sK[j * 129 + d0 + r];
#pragma unroll
            for (int cc = 0; cc < 4; cc++) {
                v0[cc] = sQV[j * 129 + e0 + cc];
                v1[cc] = sQV[j * 129 + e0 + 64 + cc];
            }
#pragma unroll
            for (int r = 0; r < 8; r++)
#pragma unroll
                for (int cc = 0; cc < 4; cc++) {
                    a0[r][cc] += kk[r] * v0[cc];
                    a1[r][cc] += kk[r] * v1[cc];
                }
        }
        const size_t kvbase = ((size_t)((b * 16 + h) * 32 + c)) * (HD_ * HD_);
#pragma unroll
        for (int r = 0; r < 8; r++)
#pragma unroll
            for (int cc = 0; cc < 4; cc++) {
                g_kv[kvbase + (size_t)(d0 + r) * HD_ + e0 + cc]      = a0[r][cc];
                g_kv[kvbase + (size_t)(d0 + r) * HD_ + e0 + 64 + cc] = a1[r][cc];
            }
    }
}

// ---------- prefix scan over chunks ----------
__global__ void scan_kernel(const float* __restrict__ rec)
{
    const int bh = blockIdx.x >> 6;
    const int e  = ((blockIdx.x & 63) << 8) + threadIdx.x;
    const float lam = expf(slope_for(bh & 15) * 64.0f);

    float st = rec[(size_t)bh * 16384 + e];
    size_t base = (size_t)bh * 32 * 16384 + e;
#pragma unroll 4
    for (int c = 0; c < 32; c++) {
        g_state[base + (size_t)c * 16384] = st;
        st = st * lam + g_kv[base + (size_t)c * 16384];
    }
}

// ---------- o_inter (norm+rope+q_dec fused) ----------
__global__ void __launch_bounds__(256, 2) o_inter_kernel(
    const float* __restrict__ qnw, const int* __restrict__ positions)
{
    extern __shared__ float sm2[];
    float* sQ  = sm2;
    float* sST = sm2 + 64 * 129;

    const int bhc = blockIdx.x;
    const int c = bhc & 31, h = (bhc >> 5) & 15, b = bhc >> 9;
    const int tid = threadIdx.x;
    const float slope = slope_for(h);
    const int ty = tid >> 4, tx = tid & 15;

    const size_t rowbase = ((size_t)(b * S_) + c * 64) * QKVW + h * HD_;
    for (int f = tid; f < 2048; f += 256) {
        int i = f >> 5, d4 = (f & 31) << 2;
        float4 q = *(const float4*)(g_qkv + rowbase + (size_t)i * QKVW + d4);
        sQ[i * 129 + d4 + 0] = q.x; sQ[i * 129 + d4 + 1] = q.y;
        sQ[i * 129 + d4 + 2] = q.z; sQ[i * 129 + d4 + 3] = q.w;
    }
    const float* st = g_state + ((size_t)((b * 16 + h) * 32 + c)) * (HD_ * HD_);
    for (int f = tid; f < 4096; f += 256) {
        int r = f >> 5, e4 = (f & 31) << 2;
        float4 v = *(const float4*)(st + (size_t)r * HD_ + e4);
        sST[r * 129 + e4 + 0] = v.x; sST[r * 129 + e4 + 1] = v.y;
        sST[r * 129 + e4 + 2] = v.z; sST[r * 129 + e4 + 3] = v.w;
    }
    __syncthreads();

    norm_rope_tile(sQ, qnw, positions, c, tid, slope, true);

    float a0[4][4] = {}, a1[4][4] = {};
    const int i0 = ty * 4, e0 = tx * 4;
    for (int d = 0; d < 128; d++) {
        float q[4], s0[4], s1[4];
#pragma unroll
        for (int r = 0; r < 4; r++) q[r] = sQ[(i0 + r) * 129 + d];
#pragma unroll
        for (int cc = 0; cc < 4; cc++) {
            s0[cc] = sST[d * 129 + e0 + cc];
            s1[cc] = sST[d * 129 + e0 + 64 + cc];
        }
#pragma unroll
        for (int r = 0; r < 4; r++)
#pragma unroll
            for (int cc = 0; cc < 4; cc++) {
                a0[r][cc] += q[r] * s0[cc];
                a1[r][cc] += q[r] * s1[cc];
            }
    }
    const size_t obase = ((size_t)(b * S_) + c * 64) * NHD + h * HD_;
#pragma unroll
    for (int r = 0; r < 4; r++)
#pragma unroll
        for (int cc = 0; cc < 4; cc++) {
            g_o[obase + (size_t)(i0 + r) * NHD + e0 + cc]      += a0[r][cc];
            g_o[obase + (size_t)(i0 + r) * NHD + e0 + 64 + cc] += a1[r][cc];
        }
}

// ---------- fused grouped RMSNorm + gate + bf16 split -> A [Ah|Al] ----------
__global__ void gating_split_kernel(const float* __restrict__ gnw,
                                    __nv_bfloat16* __restrict__ a2)
{
    const int row = blockIdx.x;
    const int w = threadIdx.x >> 5, l = threadIdx.x & 31;
    const int col = w * 256 + l * 8;

    const float* op = g_o    + (size_t)row * NHD + col;
    const float* gp = g_gate + (size_t)row * NHD + col;
    const float* wp = gnw    + col;

    float4 a0 = *(const float4*)(op);
    float4 a1 = *(const float4*)(op + 4);
    float ss = a0.x * a0.x + a0.y * a0.y + a0.z * a0.z + a0.w * a0.w
             + a1.x * a1.x + a1.y * a1.y + a1.z * a1.z + a1.w * a1.w;
#pragma unroll
    for (int o = 16; o > 0; o >>= 1) ss += __shfl_xor_sync(0xffffffffu, ss, o);
    float scale = rsqrtf(ss * (1.0f / 256.0f) + 1e-6f);

    float4 g0 = *(const float4*)(gp);
    float4 g1 = *(const float4*)(gp + 4);
    float4 w0 = *(const float4*)(wp);
    float4 w1 = *(const float4*)(wp + 4);

    float v[8];
    v[0] = a0.x * scale * w0.x / (1.0f + expf(-g0.x));
    v[1] = a0.y * scale * w0.y / (1.0f + expf(-g0.y));
    v[2] = a0.z * scale * w0.z / (1.0f + expf(-g0.z));
    v[3] = a0.w * scale * w0.w / (1.0f + expf(-g0.w));
    v[4] = a1.x * scale * w1.x / (1.0f + expf(-g1.x));
    v[5] = a1.y * scale * w1.y / (1.0f + expf(-g1.y));
    v[6] = a1.z * scale * w1.z / (1.0f + expf(-g1.z));
    v[7] = a1.w * scale * w1.w / (1.0f + expf(-g1.w));

    __nv_bfloat16 h[8], lo[8];
#pragma unroll
    for (int i = 0; i < 8; i++) split2(v[i], h[i], lo[i]);

    __nv_bfloat16* o = a2 + (size_t)row * 4096;
    *(uint4*)(o + col)        = *(const uint4*)h;
    *(uint4*)(o + 2048 + col) = *(const uint4*)lo;
}

// ================================ launcher ===================================
extern "C" void kernel_launch(void* const* d_in, const int* in_sizes, int n_in,
                              void* d_out, int out_size)
{
    const int*   positions = (const int*)d_in[0];
    const float* hidden    = (const float*)d_in[1];
    const float* rec       = (const float*)d_in[2];
    const float* w_qkv     = (const float*)d_in[3];
    const float* w_g       = (const float*)d_in[4];
    const float* w_dense   = (const float*)d_in[5];
    const float* qnw       = (const float*)d_in[6];
    const float* knw       = (const float*)d_in[7];
    const float* gnw       = (const float*)d_in[8];
    float* out = (float*)d_out;

    float *qkvp, *op, *gatep;
    __nv_bfloat16 *a2p, *w2p;
    cudaGetSymbolAddress((void**)&qkvp,  g_qkv);
    cudaGetSymbolAddress((void**)&op,    g_o);
    cudaGetSymbolAddress((void**)&gatep, g_gate);
    cudaGetSymbolAddress((void**)&a2p,   g_a2);
    cudaGetSymbolAddress((void**)&w2p,   g_w2);
    __nv_bfloat16* wF = w2p;                // fused [4096, 8192]
    __nv_bfloat16* wD = w2p + 33554432;     // dense [4096, 2048]

    const int GSM   = 3 * STG_H * 2;                              // 107520 B
    const int SMEM3 = (2 * 64 * 129 + 64 * 65 + 64) * 4;          // 82944
    const int SMEM6 = (64 * 129 + 128 * 129) * 4;                 // 99072
    cudaFuncSetAttribute(gemm_bf16, cudaFuncAttributeMaxDynamicSharedMemorySize, GSM);
    cudaFuncSetAttribute(chunk_stats_kernel, cudaFuncAttributeMaxDynamicSharedMemorySize, SMEM3);
    cudaFuncSetAttribute(o_inter_kernel, cudaFuncAttributeMaxDynamicSharedMemorySize, SMEM6);

    // launch order puts the fused GEMM at the ncu-profiled index 3
    split_A2<<<8192, 256>>>(hidden, a2p, 2048);                               // 0
    split_B2<<<12288, 256>>>(w_qkv, wF, 2048, 6144, 8192, 0);                 // 1
    split_B2<<<4096, 256>>>(w_g,    wF, 2048, 2048, 8192, 6144);              // 2
    // 3) fused QKV+gate projection  <-- profiled
    gemm_bf16<<<dim3(64, 32), 256, GSM>>>(a2p, wF, qkvp, gatep, 4096, QKVW, NHD, 8192);
    chunk_stats_kernel<<<B_ * NH_ * NC_, 256, SMEM3>>>(qnw, knw, positions);  // 4
    scan_kernel<<<2048, 256>>>(rec);                                          // 5
    o_inter_kernel<<<B_ * NH_ * NC_, 256, SMEM6>>>(qnw, positions);           // 6
    split_B2<<<4096, 256>>>(w_dense, wD, 2048, 2048, 2048, 0);                // 7
    gating_split_kernel<<<B_ * S_, 256>>>(gnw, a2p);                          // 8
    // 9) dense projection -> d_out
    gemm_bf16<<<dim3(16, 32), 256, GSM>>>(a2p, wD, out, nullptr, 4096, NHD, 0, 2048);
}

// round 13
// speedup vs baseline: 1.1712x; 1.1712x over previous
#include <cuda_runtime.h>
#include <mma.h>
#include <cuda_bf16.h>
#include <math.h>
#include <stdint.h>

using namespace nvcuda;

#define B_    2
#define S_    2048
#define NH_   16
#define HD_   128
#define NC_   32
#define QKVW  6144
#define NHD   2048

__device__ float g_qkv[(size_t)B_ * S_ * QKVW];
__device__ float g_kv[(size_t)B_ * NH_ * NC_ * HD_ * HD_];
__device__ float g_state[(size_t)B_ * NH_ * NC_ * HD_ * HD_];
__device__ float g_o[(size_t)B_ * S_ * NHD];
__device__ float g_gate[(size_t)B_ * S_ * NHD];
__device__ __nv_bfloat16 g_a2[16777216];   // A [4096, 4096] = [Ah | Al]
__device__ __nv_bfloat16 g_w2[41943040];   // fused [4096,8192]=[Bh;Bl] qkv|g, then dense [4096,2048]

__device__ __forceinline__ float slope_for(int h) {
    return -exp2f(-0.5f * (float)(h + 1)) * (1.0f + 1e-5f);
}
__device__ __forceinline__ uint32_t smem_u32(const void* p) {
    uint32_t a;
    asm("{ .reg .u64 t; cvta.to.shared.u64 t, %1; cvt.u32.u64 %0, t; }" : "=r"(a) : "l"(p));
    return a;
}
__device__ __forceinline__ void cp_async16(uint32_t sa, const void* ga) {
    asm volatile("cp.async.cg.shared.global [%0], [%1], 16;" :: "r"(sa), "l"(ga));
}
__device__ __forceinline__ void split2(float x, __nv_bfloat16& h, __nv_bfloat16& l) {
    h = __float2bfloat16(x);
    l = __float2bfloat16(x - __bfloat162float(h));
}

// ---------- split A [M,K] fp32 -> [M,2K] bf16 as (Ah | Al) ----------
__global__ void split_A2(const float* __restrict__ in, __nv_bfloat16* __restrict__ out, int K) {
    size_t idx = ((size_t)blockIdx.x * 256 + threadIdx.x) * 4;
    int m = (int)(idx / K), k = (int)(idx % K);
    float4 v = *(const float4*)(in + idx);
    __nv_bfloat16 h[4], l[4];
    split2(v.x, h[0], l[0]); split2(v.y, h[1], l[1]);
    split2(v.z, h[2], l[2]); split2(v.w, h[3], l[3]);
    __nv_bfloat16* o = out + (size_t)m * 2 * K;
    *(uint2*)(o + k)     = *(const uint2*)h;
    *(uint2*)(o + K + k) = *(const uint2*)l;
}

// ---------- split B [K,N] fp32 -> rows (Bh ; Bl) ----------
__global__ void split_B2(const float* __restrict__ in, __nv_bfloat16* __restrict__ out,
                         int K, int N, int ldo, int col_off) {
    size_t idx = ((size_t)blockIdx.x * 256 + threadIdx.x) * 4;
    int k = (int)(idx / N), n = (int)(idx % N);
    float4 v = *(const float4*)(in + idx);
    __nv_bfloat16 h[4], l[4];
    split2(v.x, h[0], l[0]); split2(v.y, h[1], l[1]);
    split2(v.z, h[2], l[2]); split2(v.w, h[3], l[3]);
    *(uint2*)(out + (size_t)k * ldo + col_off + n)       = *(const uint2*)h;
    *(uint2*)(out + (size_t)(K + k) * ldo + col_off + n) = *(const uint2*)l;
}

// ---------- bf16 split-GEMM, dual output (r11 config — frozen) ----------
// CTA 128x128, 128 threads = 4 warps (2x2), warp tile 64x64, 3-stage ring,
// single barrier per K-tile, 2 CTAs/SM.
// Logical K' = 96 tiles: 0-31 Ah@Bh, 32-63 Al@Bh, 64-95 Ah@Bl.
#define AS_LD 72
#define BS_LD 136
#define STG_H (128 * AS_LD + 64 * BS_LD)   // 17920 halves / stage

typedef wmma::fragment<wmma::matrix_a, 16, 16, 16, __nv_bfloat16, wmma::row_major> FragA;
typedef wmma::fragment<wmma::matrix_b, 16, 16, 16, __nv_bfloat16, wmma::row_major> FragB;

__global__ void __launch_bounds__(128, 2)
gemm_bf16(const __nv_bfloat16* __restrict__ A, const __nv_bfloat16* __restrict__ Bm,
          float* __restrict__ C1, float* __restrict__ C2,
          int M, int N1, int N2, int ldb)
{
    extern __shared__ __nv_bfloat16 smh[];

    const int tid = threadIdx.x, warp = tid >> 5;
    const int wr = warp >> 1, wc = warp & 1;
    const int bm = blockIdx.y * 128, bn = blockIdx.x * 128;

    __nv_bfloat16* pA[3];
    __nv_bfloat16* pB[3];
    uint32_t uA[3], uB[3];
#pragma unroll
    for (int s = 0; s < 3; s++) {
        pA[s] = smh + s * STG_H;
        pB[s] = pA[s] + 128 * AS_LD;
        uA[s] = smem_u32(pA[s]);
        uB[s] = smem_u32(pB[s]);
    }

    wmma::fragment<wmma::accumulator, 16, 16, 16, float> acc[4][4];
#pragma unroll
    for (int i = 0; i < 4; i++)
#pragma unroll
        for (int j = 0; j < 4; j++) wmma::fill_fragment(acc[i][j], 0.0f);

    auto load_stage = [&](int s, int i) {
        const int kA = ((i < 64) ? i : i - 64) << 6;
        const int kB = ((i < 32) ? i : i - 32) << 6;
#pragma unroll
        for (int j = 0; j < 8; j++) {            // A: 128 rows x 64 halves
            int id = tid + j * 128;
            int r = id >> 3, c = (id & 7) << 3;
            cp_async16(uA[s] + (uint32_t)(r * AS_LD + c) * 2u,
                       A + (size_t)(bm + r) * 4096 + kA + c);
        }
#pragma unroll
        for (int j = 0; j < 8; j++) {            // B: 64 rows x 128 halves
            int id = tid + j * 128;
            int r = id >> 4, c = (id & 15) << 3;
            cp_async16(uB[s] + (uint32_t)(r * BS_LD + c) * 2u,
                       Bm + (size_t)(kB + r) * ldb + bn + c);
        }
        asm volatile("cp.async.commit_group;" ::: "memory");
    };

    const int nk = 96;
    load_stage(0, 0);
    load_stage(1, 1);

    for (int i = 0; i < nk; i++) {
        const int s = i % 3;
        if (i < nk - 1) {
            asm volatile("cp.async.wait_group 1;" ::: "memory");
        } else {
            asm volatile("cp.async.wait_group 0;" ::: "memory");
        }
        __syncthreads();                       // also retires reads of stage (i-1)%3
        if (i + 2 < nk) load_stage((i + 2) % 3, i + 2);

        const __nv_bfloat16* a0 = pA[s] + wr * 64 * AS_LD;
        const __nv_bfloat16* b0 = pB[s] + wc * 64;
#pragma unroll
        for (int kk = 0; kk < 64; kk += 16) {
            FragA af[4];
            FragB bf[4];
#pragma unroll
            for (int x = 0; x < 4; x++)
                wmma::load_matrix_sync(af[x], a0 + x * 16 * AS_LD + kk, AS_LD);
#pragma unroll
            for (int y = 0; y < 4; y++)
                wmma::load_matrix_sync(bf[y], b0 + kk * BS_LD + y * 16, BS_LD);
#pragma unroll
            for (int x = 0; x < 4; x++)
#pragma unroll
                for (int y = 0; y < 4; y++)
                    wmma::mma_sync(acc[x][y], af[x], bf[y], acc[x][y]);
        }
    }

    if (bn < N1) {
#pragma unroll
        for (int x = 0; x < 4; x++)
#pragma unroll
            for (int y = 0; y < 4; y++)
                wmma::store_matrix_sync(C1 + (size_t)(bm + wr * 64 + x * 16) * N1 + bn + wc * 64 + y * 16,
                                        acc[x][y], N1, wmma::mem_row_major);
    } else {
        const int bn2 = bn - N1;
#pragma unroll
        for (int x = 0; x < 4; x++)
#pragma unroll
            for (int y = 0; y < 4; y++)
                wmma::store_matrix_sync(C2 + (size_t)(bm + wr * 64 + x * 16) * N2 + bn2 + wc * 64 + y * 16,
                                        acc[x][y], N2, wmma::mem_row_major);
    }
}

// ======= fused per-row RMSNorm + partial RoPE on a 64x129 smem tile ==========
__device__ __forceinline__ void norm_rope_tile(float* st, const float* __restrict__ w,
                                               const int* __restrict__ positions,
                                               int c, int tid)
{
    const int r = tid >> 2, t4 = tid & 3;
    float ss = 0.0f;
#pragma unroll 8
    for (int d = t4 * 32; d < t4 * 32 + 32; d++) {
        float a = st[r * 129 + d];
        ss += a * a;
    }
    ss += __shfl_xor_sync(0xffffffffu, ss, 1);
    ss += __shfl_xor_sync(0xffffffffu, ss, 2);
    float f = rsqrtf(ss * (1.0f / 128.0f) + 1e-6f);
#pragma unroll 8
    for (int d = t4 * 32; d < t4 * 32 + 32; d++)
        st[r * 129 + d] *= f * w[d];
    __syncthreads();
    for (int p = tid; p < 64 * 32; p += 256) {
        int rr = p >> 5, j = p & 31;
        float pos = (float)positions[c * 64 + rr];
        float inv = exp2f(-(float)j * (13.287712379549449f / 32.0f));
        float ang = pos * inv;
        float cs = cosf(ang), sn = sinf(ang);
        float x1 = st[rr * 129 + j], x2 = st[rr * 129 + j + 32];
        st[rr * 129 + j]      = x1 * cs - x2 * sn;
        st[rr * 129 + j + 32] = x2 * cs + x1 * sn;
    }
    __syncthreads();
}

// ---------- per-chunk intra output + KV; ALSO writes normalized q back -------
__global__ void __launch_bounds__(256, 2) chunk_stats_kernel(
    const float* __restrict__ qnw, const float* __restrict__ knw,
    const int* __restrict__ positions)
{
    extern __shared__ float sm[];
    float* sK   = sm;
    float* sQV  = sm + 64 * 129;
    float* sS   = sm + 2 * 64 * 129;
    float* sdec = sS + 64 * 65;

    const int bhc = blockIdx.x;
    const int c = bhc & 31, h = (bhc >> 5) & 15, b = bhc >> 9;
    const int tid = threadIdx.x;
    const float slope = slope_for(h);
    const int ty = tid >> 4, tx = tid & 15;

    const size_t rowbase = ((size_t)(b * S_) + c * 64) * QKVW + h * HD_;

    for (int f = tid; f < 2048; f += 256) {
        int i = f >> 5, d4 = (f & 31) << 2;
        const float* gp = g_qkv + rowbase + (size_t)i * QKVW + d4;
        float4 q = *(const float4*)(gp);
        float4 k = *(const float4*)(gp + 2048);
        sQV[i * 129 + d4 + 0] = q.x; sQV[i * 129 + d4 + 1] = q.y;
        sQV[i * 129 + d4 + 2] = q.z; sQV[i * 129 + d4 + 3] = q.w;
        sK[i * 129 + d4 + 0] = k.x;  sK[i * 129 + d4 + 1] = k.y;
        sK[i * 129 + d4 + 2] = k.z;  sK[i * 129 + d4 + 3] = k.w;
    }
    if (tid < 64) sdec[tid] = expf(slope * (float)(63 - tid));
    __syncthreads();

    norm_rope_tile(sQV, qnw, positions, c, tid);
    norm_rope_tile(sK,  knw, positions, c, tid);

    // write normalized+roped q back in place (o_inter consumes it without re-norm)
    for (int f = tid; f < 2048; f += 256) {
        int i = f >> 5, d4 = (f & 31) << 2;
        float4 q;
        q.x = sQV[i * 129 + d4 + 0]; q.y = sQV[i * 129 + d4 + 1];
        q.z = sQV[i * 129 + d4 + 2]; q.w = sQV[i * 129 + d4 + 3];
        *(float4*)(g_qkv + rowbase + (size_t)i * QKVW + d4) = q;
    }

    {   // scores 4x4 per thread
        float a[4][4] = {};
        const int i0 = ty * 4, j0 = tx * 4;
        for (int d = 0; d < 128; d++) {
            float q[4], kk[4];
#pragma unroll
            for (int r = 0; r < 4; r++) q[r] = sQV[(i0 + r) * 129 + d];
#pragma unroll
            for (int cc = 0; cc < 4; cc++) kk[cc] = sK[(j0 + cc) * 129 + d];
#pragma unroll
            for (int r = 0; r < 4; r++)
#pragma unroll
                for (int cc = 0; cc < 4; cc++) a[r][cc] += q[r] * kk[cc];
        }
#pragma unroll
        for (int r = 0; r < 4; r++)
#pragma unroll
            for (int cc = 0; cc < 4; cc++) {
                int i = i0 + r, j = j0 + cc;
                sS[i * 65 + j] = (i >= j) ? a[r][cc] * expf(slope * (float)(i - j)) : 0.0f;
            }
    }
    __syncthreads();

    for (int f = tid; f < 2048; f += 256) {
        int i = f >> 5, d4 = (f & 31) << 2;
        float4 v = *(const float4*)(g_qkv + rowbase + (size_t)i * QKVW + 4096 + d4);
        sQV[i * 129 + d4 + 0] = v.x; sQV[i * 129 + d4 + 1] = v.y;
        sQV[i * 129 + d4 + 2] = v.z; sQV[i * 129 + d4 + 3] = v.w;
        float kd = sdec[i];
        sK[i * 129 + d4 + 0] *= kd; sK[i * 129 + d4 + 1] *= kd;
        sK[i * 129 + d4 + 2] *= kd; sK[i * 129 + d4 + 3] *= kd;
    }
    __syncthreads();

    const size_t obase = ((size_t)(b * S_) + c * 64) * NHD + h * HD_;
    {   // o_intra
        float a0[4][4] = {}, a1[4][4] = {};
        const int i0 = ty * 4, e0 = tx * 4;
        for (int j = 0; j < 64; j++) {
            float s[4], v0[4], v1[4];
#pragma unroll
            for (int r = 0; r < 4; r++) s[r] = sS[(i0 + r) * 65 + j];
#pragma unroll
            for (int cc = 0; cc < 4; cc++) {
                v0[cc] = sQV[j * 129 + e0 + cc];
                v1[cc] = sQV[j * 129 + e0 + 64 + cc];
            }
#pragma unroll
            for (int r = 0; r < 4; r++)
#pragma unroll
                for (int cc = 0; cc < 4; cc++) {
                    a0[r][cc] += s[r] * v0[cc];
                    a1[r][cc] += s[r] * v1[cc];
                }
        }
#pragma unroll
        for (int r = 0; r < 4; r++)
#pragma unroll
            for (int cc = 0; cc < 4; cc++) {
                g_o[obase + (size_t)(i0 + r) * NHD + e0 + cc]      = a0[r][cc];
                g_o[obase + (size_t)(i0 + r) * NHD + e0 + 64 + cc] = a1[r][cc];
            }
    }

    {   // KV
        float a0[8][4] = {}, a1[8][4] = {};
        const int d0 = ty * 8, e0 = tx * 4;
        for (int j = 0; j < 64; j++) {
            float kk[8], v0[4], v1[4];
#pragma unroll
            for (int r = 0; r < 8; r++) kk[r] = sK[j * 129 + d0 + r];
#pragma unroll
            for (int cc = 0; cc < 4; cc++) {
                v0[cc] = sQV[j * 129 + e0 + cc];
                v1[cc] = sQV[j * 129 + e0 + 64 + cc];
            }
#pragma unroll
            for (int r = 0; r < 8; r++)
#pragma unroll
                for (int cc = 0; cc < 4; cc++) {
                    a0[r][cc] += kk[r] * v0[cc];
                    a1[r][cc] += kk[r] * v1[cc];
                }
        }
        const size_t kvbase = ((size_t)((b * 16 + h) * 32 + c)) * (HD_ * HD_);
#pragma unroll
        for (int r = 0; r < 8; r++)
#pragma unroll
            for (int cc = 0; cc < 4; cc++) {
                g_kv[kvbase + (size_t)(d0 + r) * HD_ + e0 + cc]      = a0[r][cc];
                g_kv[kvbase + (size_t)(d0 + r) * HD_ + e0 + 64 + cc] = a1[r][cc];
            }
    }
}

// ---------- prefix scan over chunks ----------
__global__ void scan_kernel(const float* __restrict__ rec)
{
    const int bh = blockIdx.x >> 6;
    const int e  = ((blockIdx.x & 63) << 8) + threadIdx.x;
    const float lam = expf(slope_for(bh & 15) * 64.0f);

    float st = rec[(size_t)bh * 16384 + e];
    size_t base = (size_t)bh * 32 * 16384 + e;
#pragma unroll 4
    for (int c = 0; c < 32; c++) {
        g_state[base + (size_t)c * 16384] = st;
        st = st * lam + g_kv[base + (size_t)c * 16384];
    }
}

// ---------- o_inter: q already normed+roped in g_qkv; apply q_dec at load ----
__global__ void __launch_bounds__(256, 2) o_inter_kernel(const int* __restrict__ positions)
{
    extern __shared__ float sm2[];
    float* sQ  = sm2;
    float* sST = sm2 + 64 * 129;

    const int bhc = blockIdx.x;
    const int c = bhc & 31, h = (bhc >> 5) & 15, b = bhc >> 9;
    const int tid = threadIdx.x;
    const float slope = slope_for(h);
    const int ty = tid >> 4, tx = tid & 15;

    const size_t rowbase = ((size_t)(b * S_) + c * 64) * QKVW + h * HD_;
    for (int f = tid; f < 2048; f += 256) {
        int i = f >> 5, d4 = (f & 31) << 2;
        float4 q = *(const float4*)(g_qkv + rowbase + (size_t)i * QKVW + d4);
        float qd = expf(slope * (float)(i + 1));
        sQ[i * 129 + d4 + 0] = q.x * qd; sQ[i * 129 + d4 + 1] = q.y * qd;
        sQ[i * 129 + d4 + 2] = q.z * qd; sQ[i * 129 + d4 + 3] = q.w * qd;
    }
    const float* st = g_state + ((size_t)((b * 16 + h) * 32 + c)) * (HD_ * HD_);
    for (int f = tid; f < 4096; f += 256) {
        int r = f >> 5, e4 = (f & 31) << 2;
        float4 v = *(const float4*)(st + (size_t)r * HD_ + e4);
        sST[r * 129 + e4 + 0] = v.x; sST[r * 129 + e4 + 1] = v.y;
        sST[r * 129 + e4 + 2] = v.z; sST[r * 129 + e4 + 3] = v.w;
    }
    __syncthreads();

    float a0[4][4] = {}, a1[4][4] = {};
    const int i0 = ty * 4, e0 = tx * 4;
    for (int d = 0; d < 128; d++) {
        float q[4], s0[4], s1[4];
#pragma unroll
        for (int r = 0; r < 4; r++) q[r] = sQ[(i0 + r) * 129 + d];
#pragma unroll
        for (int cc = 0; cc < 4; cc++) {
            s0[cc] = sST[d * 129 + e0 + cc];
            s1[cc] = sST[d * 129 + e0 + 64 + cc];
        }
#pragma unroll
        for (int r = 0; r < 4; r++)
#pragma unroll
            for (int cc = 0; cc < 4; cc++) {
                a0[r][cc] += q[r] * s0[cc];
                a1[r][cc] += q[r] * s1[cc];
            }
    }
    const size_t obase = ((size_t)(b * S_) + c * 64) * NHD + h * HD_;
#pragma unroll
    for (int r = 0; r < 4; r++)
#pragma unroll
        for (int cc = 0; cc < 4; cc++) {
            g_o[obase + (size_t)(i0 + r) * NHD + e0 + cc]      += a0[r][cc];
            g_o[obase + (size_t)(i0 + r) * NHD + e0 + 64 + cc] += a1[r][cc];
        }
}

// ---------- fused grouped RMSNorm + gate + bf16 split -> A [Ah|Al] ----------
__global__ void gating_split_kernel(const float* __restrict__ gnw,
                                    __nv_bfloat16* __restrict__ a2)
{
    const int row = blockIdx.x;
    const int w = threadIdx.x >> 5, l = threadIdx.x & 31;
    const int col = w * 256 + l * 8;

    const float* op = g_o    + (size_t)row * NHD + col;
    const float* gp = g_gate + (size_t)row * NHD + col;
    const float* wp = gnw    + col;

    float4 a0 = *(const float4*)(op);
    float4 a1 = *(const float4*)(op + 4);
    float ss = a0.x * a0.x + a0.y * a0.y + a0.z * a0.z + a0.w * a0.w
             + a1.x * a1.x + a1.y * a1.y + a1.z * a1.z + a1.w * a1.w;
#pragma unroll
    for (int o = 16; o > 0; o >>= 1) ss += __shfl_xor_sync(0xffffffffu, ss, o);
    float scale = rsqrtf(ss * (1.0f / 256.0f) + 1e-6f);

    float4 g0 = *(const float4*)(gp);
    float4 g1 = *(const float4*)(gp + 4);
    float4 w0 = *(const float4*)(wp);
    float4 w1 = *(const float4*)(wp + 4);

    float v[8];
    v[0] = a0.x * scale * w0.x / (1.0f + expf(-g0.x));
    v[1] = a0.y * scale * w0.y / (1.0f + expf(-g0.y));
    v[2] = a0.z * scale * w0.z / (1.0f + expf(-g0.z));
    v[3] = a0.w * scale * w0.w / (1.0f + expf(-g0.w));
    v[4] = a1.x * scale * w1.x / (1.0f + expf(-g1.x));
    v[5] = a1.y * scale * w1.y / (1.0f + expf(-g1.y));
    v[6] = a1.z * scale * w1.z / (1.0f + expf(-g1.z));
    v[7] = a1.w * scale * w1.w / (1.0f + expf(-g1.w));

    __nv_bfloat16 h[8], lo[8];
#pragma unroll
    for (int i = 0; i < 8; i++) split2(v[i], h[i], lo[i]);

    __nv_bfloat16* o = a2 + (size_t)row * 4096;
    *(uint4*)(o + col)        = *(const uint4*)h;
    *(uint4*)(o + 2048 + col) = *(const uint4*)lo;
}

// ================================ launcher ===================================
extern "C" void kernel_launch(void* const* d_in, const int* in_sizes, int n_in,
                              void* d_out, int out_size)
{
    const int*   positions = (const int*)d_in[0];
    const float* hidden    = (const float*)d_in[1];
    const float* rec       = (const float*)d_in[2];
    const float* w_qkv     = (const float*)d_in[3];
    const float* w_g       = (const float*)d_in[4];
    const float* w_dense   = (const float*)d_in[5];
    const float* qnw       = (const float*)d_in[6];
    const float* knw       = (const float*)d_in[7];
    const float* gnw       = (const float*)d_in[8];
    float* out = (float*)d_out;

    float *qkvp, *op, *gatep;
    __nv_bfloat16 *a2p, *w2p;
    cudaGetSymbolAddress((void**)&qkvp,  g_qkv);
    cudaGetSymbolAddress((void**)&op,    g_o);
    cudaGetSymbolAddress((void**)&gatep, g_gate);
    cudaGetSymbolAddress((void**)&a2p,   g_a2);
    cudaGetSymbolAddress((void**)&w2p,   g_w2);
    __nv_bfloat16* wF = w2p;                // fused [4096, 8192]
    __nv_bfloat16* wD = w2p + 33554432;     // dense [4096, 2048]

    const int GSM   = 3 * STG_H * 2;                              // 107520 B
    const int SMEM3 = (2 * 64 * 129 + 64 * 65 + 64) * 4;          // 82944
    const int SMEM6 = (64 * 129 + 128 * 129) * 4;                 // 99072
    cudaFuncSetAttribute(gemm_bf16, cudaFuncAttributeMaxDynamicSharedMemorySize, GSM);
    cudaFuncSetAttribute(chunk_stats_kernel, cudaFuncAttributeMaxDynamicSharedMemorySize, SMEM3);
    cudaFuncSetAttribute(o_inter_kernel, cudaFuncAttributeMaxDynamicSharedMemorySize, SMEM6);

    // launch order puts the fused GEMM at the ncu-profiled index 3
    split_A2<<<8192, 256>>>(hidden, a2p, 2048);                               // 0
    split_B2<<<12288, 256>>>(w_qkv, wF, 2048, 6144, 8192, 0);                 // 1
    split_B2<<<4096, 256>>>(w_g,    wF, 2048, 2048, 8192, 6144);              // 2
    // 3) fused QKV+gate projection  <-- profiled
    gemm_bf16<<<dim3(64, 32), 128, GSM>>>(a2p, wF, qkvp, gatep, 4096, QKVW, NHD, 8192);
    chunk_stats_kernel<<<B_ * NH_ * NC_, 256, SMEM3>>>(qnw, knw, positions);  // 4
    scan_kernel<<<2048, 256>>>(rec);                                          // 5
    o_inter_kernel<<<B_ * NH_ * NC_, 256, SMEM6>>>(positions);                // 6
    split_B2<<<4096, 256>>>(w_dense, wD, 2048, 2048, 2048, 0);                // 7
    gating_split_kernel<<<B_ * S_, 256>>>(gnw, a2p);                          // 8
    // 9) dense projection -> d_out
    gemm_bf16<<<dim3(16, 32), 128, GSM>>>(a2p, wD, out, nullptr, 4096, NHD, 0, 2048);
}

// round 14
// speedup vs baseline: 1.5413x; 1.3160x over previous
#include <cuda_runtime.h>
#include <mma.h>
#include <cuda_fp16.h>
#include <math.h>
#include <stdint.h>

using namespace nvcuda;

#define B_    2
#define S_    2048
#define NH_   16
#define HD_   128
#define NC_   32
#define QKVW  6144
#define NHD   2048

__device__ float g_qkv[(size_t)B_ * S_ * QKVW];
__device__ float g_kv[(size_t)B_ * NH_ * NC_ * HD_ * HD_];
__device__ float g_state[(size_t)B_ * NH_ * NC_ * HD_ * HD_];
__device__ float g_o[(size_t)B_ * S_ * NHD];
__device__ float g_gate[(size_t)B_ * S_ * NHD];
__device__ __half g_a2[16777216];   // A [4096, 4096] = [Ah | Al] fp16
__device__ __half g_w2[20971520];   // Bh fp16: fused qkv|g [2048,8192], dense [2048,2048]

__device__ __forceinline__ float slope_for(int h) {
    return -exp2f(-0.5f * (float)(h + 1)) * (1.0f + 1e-5f);
}
__device__ __forceinline__ uint32_t smem_u32(const void* p) {
    uint32_t a;
    asm("{ .reg .u64 t; cvta.to.shared.u64 t, %1; cvt.u32.u64 %0, t; }" : "=r"(a) : "l"(p));
    return a;
}
__device__ __forceinline__ void cp_async16(uint32_t sa, const void* ga) {
    asm volatile("cp.async.cg.shared.global [%0], [%1], 16;" :: "r"(sa), "l"(ga));
}
__device__ __forceinline__ void split2h(float x, __half& h, __half& l) {
    h = __float2half_rn(x);
    l = __float2half_rn(x - __half2float(h));
}

// ---------- split A [M,K] fp32 -> [M,2K] fp16 as (Ah | Al) ----------
__global__ void split_A2(const float* __restrict__ in, __half* __restrict__ out, int K) {
    size_t idx = ((size_t)blockIdx.x * 256 + threadIdx.x) * 4;
    int m = (int)(idx / K), k = (int)(idx % K);
    float4 v = *(const float4*)(in + idx);
    __half h[4], l[4];
    split2h(v.x, h[0], l[0]); split2h(v.y, h[1], l[1]);
    split2h(v.z, h[2], l[2]); split2h(v.w, h[3], l[3]);
    __half* o = out + (size_t)m * 2 * K;
    *(uint2*)(o + k)     = *(const uint2*)h;
    *(uint2*)(o + K + k) = *(const uint2*)l;
}

// ---------- round B [K,N] fp32 -> fp16 (single copy, strided dest) ----------
__global__ void round_Bh(const float* __restrict__ in, __half* __restrict__ out,
                         int N, int ldo, int col_off) {
    size_t idx = ((size_t)blockIdx.x * 256 + threadIdx.x) * 4;
    int k = (int)(idx / N), n = (int)(idx % N);
    float4 v = *(const float4*)(in + idx);
    __half h[4];
    h[0] = __float2half_rn(v.x); h[1] = __float2half_rn(v.y);
    h[2] = __float2half_rn(v.z); h[3] = __float2half_rn(v.w);
    *(uint2*)(out + (size_t)k * ldo + col_off + n) = *(const uint2*)h;
}

// ---------- fp16 2-term split-GEMM, dual output (frozen r11 structure) -------
// Logical K' = 64 tiles of 64: tile i uses A cols i*64 (Ah for 0-31, Al for
// 32-63) and B rows (i&31)*64. C = Ah@Bh + Al@Bh = A@Bh to fp32-like accuracy
// in A; B carries one-sided fp16 rounding (measured-calibrated ~4.3e-4).
// CTA 128x128, 128 threads = 4 warps (2x2), warp tile 64x64, 3-stage ring,
// single barrier per K-tile, 2 CTAs/SM.
#define AS_LD 72
#define BS_LD 136
#define STG_H (128 * AS_LD + 64 * BS_LD)   // 17920 halves / stage

typedef wmma::fragment<wmma::matrix_a, 16, 16, 16, __half, wmma::row_major> FragA;
typedef wmma::fragment<wmma::matrix_b, 16, 16, 16, __half, wmma::row_major> FragB;

__global__ void __launch_bounds__(128, 2)
gemm_fp16(const __half* __restrict__ A, const __half* __restrict__ Bm,
          float* __restrict__ C1, float* __restrict__ C2,
          int M, int N1, int N2, int ldb)
{
    extern __shared__ __half smh[];

    const int tid = threadIdx.x, warp = tid >> 5;
    const int wr = warp >> 1, wc = warp & 1;
    const int bm = blockIdx.y * 128, bn = blockIdx.x * 128;

    __half* pA[3];
    __half* pB[3];
    uint32_t uA[3], uB[3];
#pragma unroll
    for (int s = 0; s < 3; s++) {
        pA[s] = smh + s * STG_H;
        pB[s] = pA[s] + 128 * AS_LD;
        uA[s] = smem_u32(pA[s]);
        uB[s] = smem_u32(pB[s]);
    }

    wmma::fragment<wmma::accumulator, 16, 16, 16, float> acc[4][4];
#pragma unroll
    for (int i = 0; i < 4; i++)
#pragma unroll
        for (int j = 0; j < 4; j++) wmma::fill_fragment(acc[i][j], 0.0f);

    auto load_stage = [&](int s, int i) {
        const int kA = i << 6;              // A cols 0..4095 ([Ah|Al])
        const int kB = (i & 31) << 6;       // B rows repeat for the Al pass
#pragma unroll
        for (int j = 0; j < 8; j++) {            // A: 128 rows x 64 halves
            int id = tid + j * 128;
            int r = id >> 3, c = (id & 7) << 3;
            cp_async16(uA[s] + (uint32_t)(r * AS_LD + c) * 2u,
                       A + (size_t)(bm + r) * 4096 + kA + c);
        }
#pragma unroll
        for (int j = 0; j < 8; j++) {            // B: 64 rows x 128 halves
            int id = tid + j * 128;
            int r = id >> 4, c = (id & 15) << 3;
            cp_async16(uB[s] + (uint32_t)(r * BS_LD + c) * 2u,
                       Bm + (size_t)(kB + r) * ldb + bn + c);
        }
        asm volatile("cp.async.commit_group;" ::: "memory");
    };

    const int nk = 64;
    load_stage(0, 0);
    load_stage(1, 1);

    for (int i = 0; i < nk; i++) {
        const int s = i % 3;
        if (i < nk - 1) {
            asm volatile("cp.async.wait_group 1;" ::: "memory");
        } else {
            asm volatile("cp.async.wait_group 0;" ::: "memory");
        }
        __syncthreads();                       // also retires reads of stage (i-1)%3
        if (i + 2 < nk) load_stage((i + 2) % 3, i + 2);

        const __half* a0 = pA[s] + wr * 64 * AS_LD;
        const __half* b0 = pB[s] + wc * 64;
#pragma unroll
        for (int kk = 0; kk < 64; kk += 16) {
            FragA af[4];
            FragB bf[4];
#pragma unroll
            for (int x = 0; x < 4; x++)
                wmma::load_matrix_sync(af[x], a0 + x * 16 * AS_LD + kk, AS_LD);
#pragma unroll
            for (int y = 0; y < 4; y++)
                wmma::load_matrix_sync(bf[y], b0 + kk * BS_LD + y * 16, BS_LD);
#pragma unroll
            for (int x = 0; x < 4; x++)
#pragma unroll
                for (int y = 0; y < 4; y++)
                    wmma::mma_sync(acc[x][y], af[x], bf[y], acc[x][y]);
        }
    }

    if (bn < N1) {
#pragma unroll
        for (int x = 0; x < 4; x++)
#pragma unroll
            for (int y = 0; y < 4; y++)
                wmma::store_matrix_sync(C1 + (size_t)(bm + wr * 64 + x * 16) * N1 + bn + wc * 64 + y * 16,
                                        acc[x][y], N1, wmma::mem_row_major);
    } else {
        const int bn2 = bn - N1;
#pragma unroll
        for (int x = 0; x < 4; x++)
#pragma unroll
            for (int y = 0; y < 4; y++)
                wmma::store_matrix_sync(C2 + (size_t)(bm + wr * 64 + x * 16) * N2 + bn2 + wc * 64 + y * 16,
                                        acc[x][y], N2, wmma::mem_row_major);
    }
}

// ======= fused per-row RMSNorm + partial RoPE on a 64x129 smem tile ==========
__device__ __forceinline__ void norm_rope_tile(float* st, const float* __restrict__ w,
                                               const int* __restrict__ positions,
                                               int c, int tid)
{
    const int r = tid >> 2, t4 = tid & 3;
    float ss = 0.0f;
#pragma unroll 8
    for (int d = t4 * 32; d < t4 * 32 + 32; d++) {
        float a = st[r * 129 + d];
        ss += a * a;
    }
    ss += __shfl_xor_sync(0xffffffffu, ss, 1);
    ss += __shfl_xor_sync(0xffffffffu, ss, 2);
    float f = rsqrtf(ss * (1.0f / 128.0f) + 1e-6f);
#pragma unroll 8
    for (int d = t4 * 32; d < t4 * 32 + 32; d++)
        st[r * 129 + d] *= f * w[d];
    __syncthreads();
    for (int p = tid; p < 64 * 32; p += 256) {
        int rr = p >> 5, j = p & 31;
        float pos = (float)positions[c * 64 + rr];
        float inv = exp2f(-(float)j * (13.287712379549449f / 32.0f));
        float ang = pos * inv;
        float cs = cosf(ang), sn = sinf(ang);
        float x1 = st[rr * 129 + j], x2 = st[rr * 129 + j + 32];
        st[rr * 129 + j]      = x1 * cs - x2 * sn;
        st[rr * 129 + j + 32] = x2 * cs + x1 * sn;
    }
    __syncthreads();
}

// ---------- per-chunk intra output + KV; writes normalized q back ------------
__global__ void __launch_bounds__(256, 2) chunk_stats_kernel(
    const float* __restrict__ qnw, const float* __restrict__ knw,
    const int* __restrict__ positions)
{
    extern __shared__ float sm[];
    float* sK   = sm;
    float* sQV  = sm + 64 * 129;
    float* sS   = sm + 2 * 64 * 129;
    float* sdec = sS + 64 * 65;

    const int bhc = blockIdx.x;
    const int c = bhc & 31, h = (bhc >> 5) & 15, b = bhc >> 9;
    const int tid = threadIdx.x;
    const float slope = slope_for(h);
    const int ty = tid >> 4, tx = tid & 15;

    const size_t rowbase = ((size_t)(b * S_) + c * 64) * QKVW + h * HD_;

    for (int f = tid; f < 2048; f += 256) {
        int i = f >> 5, d4 = (f & 31) << 2;
        const float* gp = g_qkv + rowbase + (size_t)i * QKVW + d4;
        float4 q = *(const float4*)(gp);
        float4 k = *(const float4*)(gp + 2048);
        sQV[i * 129 + d4 + 0] = q.x; sQV[i * 129 + d4 + 1] = q.y;
        sQV[i * 129 + d4 + 2] = q.z; sQV[i * 129 + d4 + 3] = q.w;
        sK[i * 129 + d4 + 0] = k.x;  sK[i * 129 + d4 + 1] = k.y;
        sK[i * 129 + d4 + 2] = k.z;  sK[i * 129 + d4 + 3] = k.w;
    }
    if (tid < 64) sdec[tid] = expf(slope * (float)(63 - tid));
    __syncthreads();

    norm_rope_tile(sQV, qnw, positions, c, tid);
    norm_rope_tile(sK,  knw, positions, c, tid);

    for (int f = tid; f < 2048; f += 256) {   // write normed+roped q back
        int i = f >> 5, d4 = (f & 31) << 2;
        float4 q;
        q.x = sQV[i * 129 + d4 + 0]; q.y = sQV[i * 129 + d4 + 1];
        q.z = sQV[i * 129 + d4 + 2]; q.w = sQV[i * 129 + d4 + 3];
        *(float4*)(g_qkv + rowbase + (size_t)i * QKVW + d4) = q;
    }

    {   // scores 4x4 per thread
        float a[4][4] = {};
        const int i0 = ty * 4, j0 = tx * 4;
        for (int d = 0; d < 128; d++) {
            float q[4], kk[4];
#pragma unroll
            for (int r = 0; r < 4; r++) q[r] = sQV[(i0 + r) * 129 + d];
#pragma unroll
            for (int cc = 0; cc < 4; cc++) kk[cc] = sK[(j0 + cc) * 129 + d];
#pragma unroll
            for (int r = 0; r < 4; r++)
#pragma unroll
                for (int cc = 0; cc < 4; cc++) a[r][cc] += q[r] * kk[cc];
        }
#pragma unroll
        for (int r = 0; r < 4; r++)
#pragma unroll
            for (int cc = 0; cc < 4; cc++) {
                int i = i0 + r, j = j0 + cc;
                sS[i * 65 + j] = (i >= j) ? a[r][cc] * expf(slope * (float)(i - j)) : 0.0f;
            }
    }
    __syncthreads();

    for (int f = tid; f < 2048; f += 256) {
        int i = f >> 5, d4 = (f & 31) << 2;
        float4 v = *(const float4*)(g_qkv + rowbase + (size_t)i * QKVW + 4096 + d4);
        sQV[i * 129 + d4 + 0] = v.x; sQV[i * 129 + d4 + 1] = v.y;
        sQV[i * 129 + d4 + 2] = v.z; sQV[i * 129 + d4 + 3] = v.w;
        float kd = sdec[i];
        sK[i * 129 + d4 + 0] *= kd; sK[i * 129 + d4 + 1] *= kd;
        sK[i * 129 + d4 + 2] *= kd; sK[i * 129 + d4 + 3] *= kd;
    }
    __syncthreads();

    const size_t obase = ((size_t)(b * S_) + c * 64) * NHD + h * HD_;
    {   // o_intra
        float a0[4][4] = {}, a1[4][4] = {};
        const int i0 = ty * 4, e0 = tx * 4;
        for (int j = 0; j < 64; j++) {
            float s[4], v0[4], v1[4];
#pragma unroll
            for (int r = 0; r < 4; r++) s[r] = sS[(i0 + r) * 65 + j];
#pragma unroll
            for (int cc = 0; cc < 4; cc++) {
                v0[cc] = sQV[j * 129 + e0 + cc];
                v1[cc] = sQV[j * 129 + e0 + 64 + cc];
            }
#pragma unroll
            for (int r = 0; r < 4; r++)
#pragma unroll
                for (int cc = 0; cc < 4; cc++) {
                    a0[r][cc] += s[r] * v0[cc];
                    a1[r][cc] += s[r] * v1[cc];
                }
        }
#pragma unroll
        for (int r = 0; r < 4; r++)
#pragma unroll
            for (int cc = 0; cc < 4; cc++) {
                g_o[obase + (size_t)(i0 + r) * NHD + e0 + cc]      = a0[r][cc];
                g_o[obase + (size_t)(i0 + r) * NHD + e0 + 64 + cc] = a1[r][cc];
            }
    }

    {   // KV
        float a0[8][4] = {}, a1[8][4] = {};
        const int d0 = ty * 8, e0 = tx * 4;
        for (int j = 0; j < 64; j++) {
            float kk[8], v0[4], v1[4];
#pragma unroll
            for (int r = 0; r < 8; r++) kk[r] = sK[j * 129 + d0 + r];
#pragma unroll
            for (int cc = 0; cc < 4; cc++) {
                v0[cc] = sQV[j * 129 + e0 + cc];
                v1[cc] = sQV[j * 129 + e0 + 64 + cc];
            }
#pragma unroll
            for (int r = 0; r < 8; r++)
#pragma unroll
                for (int cc = 0; cc < 4; cc++) {
                    a0[r][cc] += kk[r] * v0[cc];
                    a1[r][cc] += kk[r] * v1[cc];
                }
        }
        const size_t kvbase = ((size_t)((b * 16 + h) * 32 + c)) * (HD_ * HD_);
#pragma unroll
        for (int r = 0; r < 8; r++)
#pragma unroll
            for (int cc = 0; cc < 4; cc++) {
                g_kv[kvbase + (size_t)(d0 + r) * HD_ + e0 + cc]      = a0[r][cc];
                g_kv[kvbase + (size_t)(d0 + r) * HD_ + e0 + 64 + cc] = a1[r][cc];
            }
    }
}

// ---------- prefix scan over chunks ----------
__global__ void scan_kernel(const float* __restrict__ rec)
{
    const int bh = blockIdx.x >> 6;
    const int e  = ((blockIdx.x & 63) << 8) + threadIdx.x;
    const float lam = expf(slope_for(bh & 15) * 64.0f);

    float st = rec[(size_t)bh * 16384 + e];
    size_t base = (size_t)bh * 32 * 16384 + e;
#pragma unroll 4
    for (int c = 0; c < 32; c++) {
        g_state[base + (size_t)c * 16384] = st;
        st = st * lam + g_kv[base + (size_t)c * 16384];
    }
}

// ---------- o_inter: q already normed+roped; apply q_dec at load ----------
__global__ void __launch_bounds__(256, 2) o_inter_kernel(const int* __restrict__ positions)
{
    extern __shared__ float sm2[];
    float* sQ  = sm2;
    float* sST = sm2 + 64 * 129;

    const int bhc = blockIdx.x;
    const int c = bhc & 31, h = (bhc >> 5) & 15, b = bhc >> 9;
    const int tid = threadIdx.x;
    const float slope = slope_for(h);
    const int ty = tid >> 4, tx = tid & 15;

    const size_t rowbase = ((size_t)(b * S_) + c * 64) * QKVW + h * HD_;
    for (int f = tid; f < 2048; f += 256) {
        int i = f >> 5, d4 = (f & 31) << 2;
        float4 q = *(const float4*)(g_qkv + rowbase + (size_t)i * QKVW + d4);
        float qd = expf(slope * (float)(i + 1));
        sQ[i * 129 + d4 + 0] = q.x * qd; sQ[i * 129 + d4 + 1] = q.y * qd;
        sQ[i * 129 + d4 + 2] = q.z * qd; sQ[i * 129 + d4 + 3] = q.w * qd;
    }
    const float* st = g_state + ((size_t)((b * 16 + h) * 32 + c)) * (HD_ * HD_);
    for (int f = tid; f < 4096; f += 256) {
        int r = f >> 5, e4 = (f & 31) << 2;
        float4 v = *(const float4*)(st + (size_t)r * HD_ + e4);
        sST[r * 129 + e4 + 0] = v.x; sST[r * 129 + e4 + 1] = v.y;
        sST[r * 129 + e4 + 2] = v.z; sST[r * 129 + e4 + 3] = v.w;
    }
    __syncthreads();

    float a0[4][4] = {}, a1[4][4] = {};
    const int i0 = ty * 4, e0 = tx * 4;
    for (int d = 0; d < 128; d++) {
        float q[4], s0[4], s1[4];
#pragma unroll
        for (int r = 0; r < 4; r++) q[r] = sQ[(i0 + r) * 129 + d];
#pragma unroll
        for (int cc = 0; cc < 4; cc++) {
            s0[cc] = sST[d * 129 + e0 + cc];
            s1[cc] = sST[d * 129 + e0 + 64 + cc];
        }
#pragma unroll
        for (int r = 0; r < 4; r++)
#pragma unroll
            for (int cc = 0; cc < 4; cc++) {
                a0[r][cc] += q[r] * s0[cc];
                a1[r][cc] += q[r] * s1[cc];
            }
    }
    const size_t obase = ((size_t)(b * S_) + c * 64) * NHD + h * HD_;
#pragma unroll
    for (int r = 0; r < 4; r++)
#pragma unroll
        for (int cc = 0; cc < 4; cc++) {
            g_o[obase + (size_t)(i0 + r) * NHD + e0 + cc]      += a0[r][cc];
            g_o[obase + (size_t)(i0 + r) * NHD + e0 + 64 + cc] += a1[r][cc];
        }
}

// ---------- fused grouped RMSNorm + gate + fp16 split -> A [Ah|Al] ----------
__global__ void gating_split_kernel(const float* __restrict__ gnw,
                                    __half* __restrict__ a2)
{
    const int row = blockIdx.x;
    const int w = threadIdx.x >> 5, l = threadIdx.x & 31;
    const int col = w * 256 + l * 8;

    const float* op = g_o    + (size_t)row * NHD + col;
    const float* gp = g_gate + (size_t)row * NHD + col;
    const float* wp = gnw    + col;

    float4 a0 = *(const float4*)(op);
    float4 a1 = *(const float4*)(op + 4);
    float ss = a0.x * a0.x + a0.y * a0.y + a0.z * a0.z + a0.w * a0.w
             + a1.x * a1.x + a1.y * a1.y + a1.z * a1.z + a1.w * a1.w;
#pragma unroll
    for (int o = 16; o > 0; o >>= 1) ss += __shfl_xor_sync(0xffffffffu, ss, o);
    float scale = rsqrtf(ss * (1.0f / 256.0f) + 1e-6f);

    float4 g0 = *(const float4*)(gp);
    float4 g1 = *(const float4*)(gp + 4);
    float4 w0 = *(const float4*)(wp);
    float4 w1 = *(const float4*)(wp + 4);

    float v[8];
    v[0] = a0.x * scale * w0.x / (1.0f + expf(-g0.x));
    v[1] = a0.y * scale * w0.y / (1.0f + expf(-g0.y));
    v[2] = a0.z * scale * w0.z / (1.0f + expf(-g0.z));
    v[3] = a0.w * scale * w0.w / (1.0f + expf(-g0.w));
    v[4] = a1.x * scale * w1.x / (1.0f + expf(-g1.x));
    v[5] = a1.y * scale * w1.y / (1.0f + expf(-g1.y));
    v[6] = a1.z * scale * w1.z / (1.0f + expf(-g1.z));
    v[7] = a1.w * scale * w1.w / (1.0f + expf(-g1.w));

    __half h[8], lo[8];
#pragma unroll
    for (int i = 0; i < 8; i++) split2h(v[i], h[i], lo[i]);

    __half* o = a2 + (size_t)row * 4096;
    *(uint4*)(o + col)        = *(const uint4*)h;
    *(uint4*)(o + 2048 + col) = *(const uint4*)lo;
}

// ================================ launcher ===================================
extern "C" void kernel_launch(void* const* d_in, const int* in_sizes, int n_in,
                              void* d_out, int out_size)
{
    const int*   positions = (const int*)d_in[0];
    const float* hidden    = (const float*)d_in[1];
    const float* rec       = (const float*)d_in[2];
    const float* w_qkv     = (const float*)d_in[3];
    const float* w_g       = (const float*)d_in[4];
    const float* w_dense   = (const float*)d_in[5];
    const float* qnw       = (const float*)d_in[6];
    const float* knw       = (const float*)d_in[7];
    const float* gnw       = (const float*)d_in[8];
    float* out = (float*)d_out;

    float *qkvp, *op, *gatep;
    __half *a2p, *w2p;
    cudaGetSymbolAddress((void**)&qkvp,  g_qkv);
    cudaGetSymbolAddress((void**)&op,    g_o);
    cudaGetSymbolAddress((void**)&gatep, g_gate);
    cudaGetSymbolAddress((void**)&a2p,   g_a2);
    cudaGetSymbolAddress((void**)&w2p,   g_w2);
    __half* wF = w2p;                // fused Bh [2048, 8192]: qkv cols 0-6143, gate 6144-8191
    __half* wD = w2p + 16777216;     // dense Bh [2048, 2048]

    const int GSM   = 3 * STG_H * 2;                              // 107520 B
    const int SMEM3 = (2 * 64 * 129 + 64 * 65 + 64) * 4;          // 82944
    const int SMEM6 = (64 * 129 + 128 * 129) * 4;                 // 99072
    cudaFuncSetAttribute(gemm_fp16, cudaFuncAttributeMaxDynamicSharedMemorySize, GSM);
    cudaFuncSetAttribute(chunk_stats_kernel, cudaFuncAttributeMaxDynamicSharedMemorySize, SMEM3);
    cudaFuncSetAttribute(o_inter_kernel, cudaFuncAttributeMaxDynamicSharedMemorySize, SMEM6);

    // launch order puts the fused GEMM at the ncu-profiled index 3
    split_A2<<<8192, 256>>>(hidden, a2p, 2048);                               // 0
    round_Bh<<<12288, 256>>>(w_qkv, wF, 6144, 8192, 0);                       // 1
    round_Bh<<<4096, 256>>>(w_g,    wF, 2048, 8192, 6144);                    // 2
    // 3) fused QKV+gate projection (K'=4096)  <-- profiled
    gemm_fp16<<<dim3(64, 32), 128, GSM>>>(a2p, wF, qkvp, gatep, 4096, QKVW, NHD, 8192);
    chunk_stats_kernel<<<B_ * NH_ * NC_, 256, SMEM3>>>(qnw, knw, positions);  // 4
    scan_kernel<<<2048, 256>>>(rec);                                          // 5
    o_inter_kernel<<<B_ * NH_ * NC_, 256, SMEM6>>>(positions);                // 6
    round_Bh<<<4096, 256>>>(w_dense, wD, 2048, 2048, 0);                      // 7
    gating_split_kernel<<<B_ * S_, 256>>>(gnw, a2p);                          // 8
    // 9) dense projection -> d_out
    gemm_fp16<<<dim3(16, 32), 128, GSM>>>(a2p, wD, out, nullptr, 4096, NHD, 0, 2048);
}

// round 16
// speedup vs baseline: 2.4349x; 1.5798x over previous
#include <cuda_runtime.h>
#include <mma.h>
#include <cuda_fp16.h>
#include <math.h>
#include <stdint.h>

using namespace nvcuda;

#define B_    2
#define S_    2048
#define NH_   16
#define HD_   128
#define NC_   32
#define QKVW  6144
#define NHD   2048

__device__ float g_qkv[(size_t)B_ * S_ * QKVW];
__device__ float g_kv[(size_t)B_ * NH_ * NC_ * HD_ * HD_];
__device__ float g_state[(size_t)B_ * NH_ * NC_ * HD_ * HD_];
__device__ float g_o[(size_t)B_ * S_ * NHD];
__device__ float g_gate[(size_t)B_ * S_ * NHD];
__device__ __half g_a2[8388608];    // A [4096, 2048] fp16
__device__ __half g_w2[20971520];   // Bh fp16: fused qkv|g [2048,8192], dense [2048,2048]

__device__ __forceinline__ float slope_for(int h) {
    return -exp2f(-0.5f * (float)(h + 1)) * (1.0f + 1e-5f);
}
__device__ __forceinline__ uint32_t smem_u32(const void* p) {
    uint32_t a;
    asm("{ .reg .u64 t; cvta.to.shared.u64 t, %1; cvt.u32.u64 %0, t; }" : "=r"(a) : "l"(p));
    return a;
}
__device__ __forceinline__ void cp_async16(uint32_t sa, const void* ga) {
    asm volatile("cp.async.cg.shared.global [%0], [%1], 16;" :: "r"(sa), "l"(ga));
}

// ---------- round A [M,K] fp32 -> fp16  (grid MUST cover M*K/4 = 2,097,152) --
__global__ void round_Ah(const float* __restrict__ in, __half* __restrict__ out) {
    size_t idx = ((size_t)blockIdx.x * 256 + threadIdx.x) * 4;
    float4 v = *(const float4*)(in + idx);
    __half h[4];
    h[0] = __float2half_rn(v.x); h[1] = __float2half_rn(v.y);
    h[2] = __float2half_rn(v.z); h[3] = __float2half_rn(v.w);
    *(uint2*)(out + idx) = *(const uint2*)h;
}

// ---------- round B [K,N] fp32 -> fp16 (strided dest for fused buffer) ----------
__global__ void round_Bh(const float* __restrict__ in, __half* __restrict__ out,
                         int N, int ldo, int col_off) {
    size_t idx = ((size_t)blockIdx.x * 256 + threadIdx.x) * 4;
    int k = (int)(idx / N), n = (int)(idx % N);
    float4 v = *(const float4*)(in + idx);
    __half h[4];
    h[0] = __float2half_rn(v.x); h[1] = __float2half_rn(v.y);
    h[2] = __float2half_rn(v.z); h[3] = __float2half_rn(v.w);
    *(uint2*)(out + (size_t)k * ldo + col_off + n) = *(const uint2*)h;
}

// ---------- pure fp16 GEMM, dual output (frozen r11 structure, K=2048) -------
// CTA 128x128, 128 threads = 4 warps (2x2), warp tile 64x64, 3-stage ring,
// single barrier per K-tile, 2 CTAs/SM. nk = 32 tiles of 64.
#define AS_LD 72
#define BS_LD 136
#define STG_H (128 * AS_LD + 64 * BS_LD)   // 17920 halves / stage

typedef wmma::fragment<wmma::matrix_a, 16, 16, 16, __half, wmma::row_major> FragA;
typedef wmma::fragment<wmma::matrix_b, 16, 16, 16, __half, wmma::row_major> FragB;

__global__ void __launch_bounds__(128, 2)
gemm_fp16(const __half* __restrict__ A, const __half* __restrict__ Bm,
          float* __restrict__ C1, float* __restrict__ C2,
          int M, int N1, int N2, int ldb)
{
    extern __shared__ __half smh[];

    const int tid = threadIdx.x, warp = tid >> 5;
    const int wr = warp >> 1, wc = warp & 1;
    const int bm = blockIdx.y * 128, bn = blockIdx.x * 128;

    __half* pA[3];
    __half* pB[3];
    uint32_t uA[3], uB[3];
#pragma unroll
    for (int s = 0; s < 3; s++) {
        pA[s] = smh + s * STG_H;
        pB[s] = pA[s] + 128 * AS_LD;
        uA[s] = smem_u32(pA[s]);
        uB[s] = smem_u32(pB[s]);
    }

    wmma::fragment<wmma::accumulator, 16, 16, 16, float> acc[4][4];
#pragma unroll
    for (int i = 0; i < 4; i++)
#pragma unroll
        for (int j = 0; j < 4; j++) wmma::fill_fragment(acc[i][j], 0.0f);

    auto load_stage = [&](int s, int i) {
        const int k0 = i << 6;
#pragma unroll
        for (int j = 0; j < 8; j++) {            // A: 128 rows x 64 halves
            int id = tid + j * 128;
            int r = id >> 3, c = (id & 7) << 3;
            cp_async16(uA[s] + (uint32_t)(r * AS_LD + c) * 2u,
                       A + (size_t)(bm + r) * 2048 + k0 + c);
        }
#pragma unroll
        for (int j = 0; j < 8; j++) {            // B: 64 rows x 128 halves
            int id = tid + j * 128;
            int r = id >> 4, c = (id & 15) << 3;
            cp_async16(uB[s] + (uint32_t)(r * BS_LD + c) * 2u,
                       Bm + (size_t)(k0 + r) * ldb + bn + c);
        }
        asm volatile("cp.async.commit_group;" ::: "memory");
    };

    const int nk = 32;
    load_stage(0, 0);
    load_stage(1, 1);

    for (int i = 0; i < nk; i++) {
        const int s = i % 3;
        if (i < nk - 1) {
            asm volatile("cp.async.wait_group 1;" ::: "memory");
        } else {
            asm volatile("cp.async.wait_group 0;" ::: "memory");
        }
        __syncthreads();                       // also retires reads of stage (i-1)%3
        if (i + 2 < nk) load_stage((i + 2) % 3, i + 2);

        const __half* a0 = pA[s] + wr * 64 * AS_LD;
        const __half* b0 = pB[s] + wc * 64;
#pragma unroll
        for (int kk = 0; kk < 64; kk += 16) {
            FragA af[4];
            FragB bf[4];
#pragma unroll
            for (int x = 0; x < 4; x++)
                wmma::load_matrix_sync(af[x], a0 + x * 16 * AS_LD + kk, AS_LD);
#pragma unroll
            for (int y = 0; y < 4; y++)
                wmma::load_matrix_sync(bf[y], b0 + kk * BS_LD + y * 16, BS_LD);
#pragma unroll
            for (int x = 0; x < 4; x++)
#pragma unroll
                for (int y = 0; y < 4; y++)
                    wmma::mma_sync(acc[x][y], af[x], bf[y], acc[x][y]);
        }
    }

    if (bn < N1) {
#pragma unroll
        for (int x = 0; x < 4; x++)
#pragma unroll
            for (int y = 0; y < 4; y++)
                wmma::store_matrix_sync(C1 + (size_t)(bm + wr * 64 + x * 16) * N1 + bn + wc * 64 + y * 16,
                                        acc[x][y], N1, wmma::mem_row_major);
    } else {
        const int bn2 = bn - N1;
#pragma unroll
        for (int x = 0; x < 4; x++)
#pragma unroll
            for (int y = 0; y < 4; y++)
                wmma::store_matrix_sync(C2 + (size_t)(bm + wr * 64 + x * 16) * N2 + bn2 + wc * 64 + y * 16,
                                        acc[x][y], N2, wmma::mem_row_major);
    }
}

// ======= fused per-row RMSNorm + partial RoPE on a 64x129 smem tile ==========
__device__ __forceinline__ void norm_rope_tile(float* st, const float* __restrict__ w,
                                               const int* __restrict__ positions,
                                               int c, int tid)
{
    const int r = tid >> 2, t4 = tid & 3;
    float ss = 0.0f;
#pragma unroll 8
    for (int d = t4 * 32; d < t4 * 32 + 32; d++) {
        float a = st[r * 129 + d];
        ss += a * a;
    }
    ss += __shfl_xor_sync(0xffffffffu, ss, 1);
    ss += __shfl_xor_sync(0xffffffffu, ss, 2);
    float f = rsqrtf(ss * (1.0f / 128.0f) + 1e-6f);
#pragma unroll 8
    for (int d = t4 * 32; d < t4 * 32 + 32; d++)
        st[r * 129 + d] *= f * w[d];
    __syncthreads();
    for (int p = tid; p < 64 * 32; p += 256) {
        int rr = p >> 5, j = p & 31;
        float pos = (float)positions[c * 64 + rr];
        float inv = exp2f(-(float)j * (13.287712379549449f / 32.0f));
        float ang = pos * inv;
        float cs = cosf(ang), sn = sinf(ang);
        float x1 = st[rr * 129 + j], x2 = st[rr * 129 + j + 32];
        st[rr * 129 + j]      = x1 * cs - x2 * sn;
        st[rr * 129 + j + 32] = x2 * cs + x1 * sn;
    }
    __syncthreads();
}

// ---------- per-chunk intra output + KV; writes normalized q back ------------
__global__ void __launch_bounds__(256, 2) chunk_stats_kernel(
    const float* __restrict__ qnw, const float* __restrict__ knw,
    const int* __restrict__ positions)
{
    extern __shared__ float sm[];
    float* sK   = sm;
    float* sQV  = sm + 64 * 129;
    float* sS   = sm + 2 * 64 * 129;
    float* sdec = sS + 64 * 65;

    const int bhc = blockIdx.x;
    const int c = bhc & 31, h = (bhc >> 5) & 15, b = bhc >> 9;
    const int tid = threadIdx.x;
    const float slope = slope_for(h);
    const int ty = tid >> 4, tx = tid & 15;

    const size_t rowbase = ((size_t)(b * S_) + c * 64) * QKVW + h * HD_;

    for (int f = tid; f < 2048; f += 256) {
        int i = f >> 5, d4 = (f & 31) << 2;
        const float* gp = g_qkv + rowbase + (size_t)i * QKVW + d4;
        float4 q = *(const float4*)(gp);
        float4 k = *(const float4*)(gp + 2048);
        sQV[i * 129 + d4 + 0] = q.x; sQV[i * 129 + d4 + 1] = q.y;
        sQV[i * 129 + d4 + 2] = q.z; sQV[i * 129 + d4 + 3] = q.w;
        sK[i * 129 + d4 + 0] = k.x;  sK[i * 129 + d4 + 1] = k.y;
        sK[i * 129 + d4 + 2] = k.z;  sK[i * 129 + d4 + 3] = k.w;
    }
    if (tid < 64) sdec[tid] = expf(slope * (float)(63 - tid));
    __syncthreads();

    norm_rope_tile(sQV, qnw, positions, c, tid);
    norm_rope_tile(sK,  knw, positions, c, tid);

    for (int f = tid; f < 2048; f += 256) {   // write normed+roped q back
        int i = f >> 5, d4 = (f & 31) << 2;
        float4 q;
        q.x = sQV[i * 129 + d4 + 0]; q.y = sQV[i * 129 + d4 + 1];
        q.z = sQV[i * 129 + d4 + 2]; q.w = sQV[i * 129 + d4 + 3];
        *(float4*)(g_qkv + rowbase + (size_t)i * QKVW + d4) = q;
    }

    {   // scores 4x4 per thread
        float a[4][4] = {};
        const int i0 = ty * 4, j0 = tx * 4;
        for (int d = 0; d < 128; d++) {
            float q[4], kk[4];
#pragma unroll
            for (int r = 0; r < 4; r++) q[r] = sQV[(i0 + r) * 129 + d];
#pragma unroll
            for (int cc = 0; cc < 4; cc++) kk[cc] = sK[(j0 + cc) * 129 + d];
#pragma unroll
            for (int r = 0; r < 4; r++)
#pragma unroll
                for (int cc = 0; cc < 4; cc++) a[r][cc] += q[r] * kk[cc];
        }
#pragma unroll
        for (int r = 0; r < 4; r++)
#pragma unroll
            for (int cc = 0; cc < 4; cc++) {
                int i = i0 + r, j = j0 + cc;
                sS[i * 65 + j] = (i >= j) ? a[r][cc] * expf(slope * (float)(i - j)) : 0.0f;
            }
    }
    __syncthreads();

    for (int f = tid; f < 2048; f += 256) {
        int i = f >> 5, d4 = (f & 31) << 2;
        float4 v = *(const float4*)(g_qkv + rowbase + (size_t)i * QKVW + 4096 + d4);
        sQV[i * 129 + d4 + 0] = v.x; sQV[i * 129 + d4 + 1] = v.y;
        sQV[i * 129 + d4 + 2] = v.z; sQV[i * 129 + d4 + 3] = v.w;
        float kd = sdec[i];
        sK[i * 129 + d4 + 0] *= kd; sK[i * 129 + d4 + 1] *= kd;
        sK[i * 129 + d4 + 2] *= kd; sK[i * 129 + d4 + 3] *= kd;
    }
    __syncthreads();

    const size_t obase = ((size_t)(b * S_) + c * 64) * NHD + h * HD_;
    {   // o_intra
        float a0[4][4] = {}, a1[4][4] = {};
        const int i0 = ty * 4, e0 = tx * 4;
        for (int j = 0; j < 64; j++) {
            float s[4], v0[4], v1[4];
#pragma unroll
            for (int r = 0; r < 4; r++) s[r] = sS[(i0 + r) * 65 + j];
#pragma unroll
            for (int cc = 0; cc < 4; cc++) {
                v0[cc] = sQV[j * 129 + e0 + cc];
                v1[cc] = sQV[j * 129 + e0 + 64 + cc];
            }
#pragma unroll
            for (int r = 0; r < 4; r++)
#pragma unroll
                for (int cc = 0; cc < 4; cc++) {
                    a0[r][cc] += s[r] * v0[cc];
                    a1[r][cc] += s[r] * v1[cc];
                }
        }
#pragma unroll
        for (int r = 0; r < 4; r++)
#pragma unroll
            for (int cc = 0; cc < 4; cc++) {
                g_o[obase + (size_t)(i0 + r) * NHD + e0 + cc]      = a0[r][cc];
                g_o[obase + (size_t)(i0 + r) * NHD + e0 + 64 + cc] = a1[r][cc];
            }
    }

    {   // KV
        float a0[8][4] = {}, a1[8][4] = {};
        const int d0 = ty * 8, e0 = tx * 4;
        for (int j = 0; j < 64; j++) {
            float kk[8], v0[4], v1[4];
#pragma unroll
            for (int r = 0; r < 8; r++) kk[r] = sK[j * 129 + d0 + r];
#pragma unroll
            for (int cc = 0; cc < 4; cc++) {
                v0[cc] = sQV[j * 129 + e0 + cc];
                v1[cc] = sQV[j * 129 + e0 + 64 + cc];
            }
#pragma unroll
            for (int r = 0; r < 8; r++)
#pragma unroll
                for (int cc = 0; cc < 4; cc++) {
                    a0[r][cc] += kk[r] * v0[cc];
                    a1[r][cc] += kk[r] * v1[cc];
                }
        }
        const size_t kvbase = ((size_t)((b * 16 + h) * 32 + c)) * (HD_ * HD_);
#pragma unroll
        for (int r = 0; r < 8; r++)
#pragma unroll
            for (int cc = 0; cc < 4; cc++) {
                g_kv[kvbase + (size_t)(d0 + r) * HD_ + e0 + cc]      = a0[r][cc];
                g_kv[kvbase + (size_t)(d0 + r) * HD_ + e0 + 64 + cc] = a1[r][cc];
            }
    }
}

// ---------- prefix scan over chunks ----------
__global__ void scan_kernel(const float* __restrict__ rec)
{
    const int bh = blockIdx.x >> 6;
    const int e  = ((blockIdx.x & 63) << 8) + threadIdx.x;
    const float lam = expf(slope_for(bh & 15) * 64.0f);

    float st = rec[(size_t)bh * 16384 + e];
    size_t base = (size_t)bh * 32 * 16384 + e;
#pragma unroll 4
    for (int c = 0; c < 32; c++) {
        g_state[base + (size_t)c * 16384] = st;
        st = st * lam + g_kv[base + (size_t)c * 16384];
    }
}

// ---------- o_inter: q already normed+roped; apply q_dec at load ----------
__global__ void __launch_bounds__(256, 2) o_inter_kernel(const int* __restrict__ positions)
{
    extern __shared__ float sm2[];
    float* sQ  = sm2;
    float* sST = sm2 + 64 * 129;

    const int bhc = blockIdx.x;
    const int c = bhc & 31, h = (bhc >> 5) & 15, b = bhc >> 9;
    const int tid = threadIdx.x;
    const float slope = slope_for(h);
    const int ty = tid >> 4, tx = tid & 15;

    const size_t rowbase = ((size_t)(b * S_) + c * 64) * QKVW + h * HD_;
    for (int f = tid; f < 2048; f += 256) {
        int i = f >> 5, d4 = (f & 31) << 2;
        float4 q = *(const float4*)(g_qkv + rowbase + (size_t)i * QKVW + d4);
        float qd = expf(slope * (float)(i + 1));
        sQ[i * 129 + d4 + 0] = q.x * qd; sQ[i * 129 + d4 + 1] = q.y * qd;
        sQ[i * 129 + d4 + 2] = q.z * qd; sQ[i * 129 + d4 + 3] = q.w * qd;
    }
    const float* st = g_state + ((size_t)((b * 16 + h) * 32 + c)) * (HD_ * HD_);
    for (int f = tid; f < 4096; f += 256) {
        int r = f >> 5, e4 = (f & 31) << 2;
        float4 v = *(const float4*)(st + (size_t)r * HD_ + e4);
        sST[r * 129 + e4 + 0] = v.x; sST[r * 129 + e4 + 1] = v.y;
        sST[r * 129 + e4 + 2] = v.z; sST[r * 129 + e4 + 3] = v.w;
    }
    __syncthreads();

    float a0[4][4] = {}, a1[4][4] = {};
    const int i0 = ty * 4, e0 = tx * 4;
    for (int d = 0; d < 128; d++) {
        float q[4], s0[4], s1[4];
#pragma unroll
        for (int r = 0; r < 4; r++) q[r] = sQ[(i0 + r) * 129 + d];
#pragma unroll
        for (int cc = 0; cc < 4; cc++) {
            s0[cc] = sST[d * 129 + e0 + cc];
            s1[cc] = sST[d * 129 + e0 + 64 + cc];
        }
#pragma unroll
        for (int r = 0; r < 4; r++)
#pragma unroll
            for (int cc = 0; cc < 4; cc++) {
                a0[r][cc] += q[r] * s0[cc];
                a1[r][cc] += q[r] * s1[cc];
            }
    }
    const size_t obase = ((size_t)(b * S_) + c * 64) * NHD + h * HD_;
#pragma unroll
    for (int r = 0; r < 4; r++)
#pragma unroll
        for (int cc = 0; cc < 4; cc++) {
            g_o[obase + (size_t)(i0 + r) * NHD + e0 + cc]      += a0[r][cc];
            g_o[obase + (size_t)(i0 + r) * NHD + e0 + 64 + cc] += a1[r][cc];
        }
}

// ---------- fused grouped RMSNorm + gate + fp16 round -> A ----------
__global__ void gating_split_kernel(const float* __restrict__ gnw,
                                    __half* __restrict__ a2)
{
    const int row = blockIdx.x;
    const int w = threadIdx.x >> 5, l = threadIdx.x & 31;
    const int col = w * 256 + l * 8;

    const float* op = g_o    + (size_t)row * NHD + col;
    const float* gp = g_gate + (size_t)row * NHD + col;
    const float* wp = gnw    + col;

    float4 a0 = *(const float4*)(op);
    float4 a1 = *(const float4*)(op + 4);
    float ss = a0.x * a0.x + a0.y * a0.y + a0.z * a0.z + a0.w * a0.w
             + a1.x * a1.x + a1.y * a1.y + a1.z * a1.z + a1.w * a1.w;
#pragma unroll
    for (int o = 16; o > 0; o >>= 1) ss += __shfl_xor_sync(0xffffffffu, ss, o);
    float scale = rsqrtf(ss * (1.0f / 256.0f) + 1e-6f);

    float4 g0 = *(const float4*)(gp);
    float4 g1 = *(const float4*)(gp + 4);
    float4 w0 = *(const float4*)(wp);
    float4 w1 = *(const float4*)(wp + 4);

    __half h[8];
    h[0] = __float2half_rn(a0.x * scale * w0.x / (1.0f + expf(-g0.x)));
    h[1] = __float2half_rn(a0.y * scale * w0.y / (1.0f + expf(-g0.y)));
    h[2] = __float2half_rn(a0.z * scale * w0.z / (1.0f + expf(-g0.z)));
    h[3] = __float2half_rn(a0.w * scale * w0.w / (1.0f + expf(-g0.w)));
    h[4] = __float2half_rn(a1.x * scale * w1.x / (1.0f + expf(-g1.x)));
    h[5] = __float2half_rn(a1.y * scale * w1.y / (1.0f + expf(-g1.y)));
    h[6] = __float2half_rn(a1.z * scale * w1.z / (1.0f + expf(-g1.z)));
    h[7] = __float2half_rn(a1.w * scale * w1.w / (1.0f + expf(-g1.w)));

    *(uint4*)(a2 + (size_t)row * 2048 + col) = *(const uint4*)h;
}

// ================================ launcher ===================================
extern "C" void kernel_launch(void* const* d_in, const int* in_sizes, int n_in,
                              void* d_out, int out_size)
{
    const int*   positions = (const int*)d_in[0];
    const float* hidden    = (const float*)d_in[1];
    const float* rec       = (const float*)d_in[2];
    const float* w_qkv     = (const float*)d_in[3];
    const float* w_g       = (const float*)d_in[4];
    const float* w_dense   = (const float*)d_in[5];
    const float* qnw       = (const float*)d_in[6];
    const float* knw       = (const float*)d_in[7];
    const float* gnw       = (const float*)d_in[8];
    float* out = (float*)d_out;

    float *qkvp, *op, *gatep;
    __half *a2p, *w2p;
    cudaGetSymbolAddress((void**)&qkvp,  g_qkv);
    cudaGetSymbolAddress((void**)&op,    g_o);
    cudaGetSymbolAddress((void**)&gatep, g_gate);
    cudaGetSymbolAddress((void**)&a2p,   g_a2);
    cudaGetSymbolAddress((void**)&w2p,   g_w2);
    __half* wF = w2p;                // fused Bh [2048, 8192]: qkv cols 0-6143, gate 6144-8191
    __half* wD = w2p + 16777216;     // dense Bh [2048, 2048]

    const int GSM   = 3 * STG_H * 2;                              // 107520 B
    const int SMEM3 = (2 * 64 * 129 + 64 * 65 + 64) * 4;          // 82944
    const int SMEM6 = (64 * 129 + 128 * 129) * 4;                 // 99072
    cudaFuncSetAttribute(gemm_fp16, cudaFuncAttributeMaxDynamicSharedMemorySize, GSM);
    cudaFuncSetAttribute(chunk_stats_kernel, cudaFuncAttributeMaxDynamicSharedMemorySize, SMEM3);
    cudaFuncSetAttribute(o_inter_kernel, cudaFuncAttributeMaxDynamicSharedMemorySize, SMEM6);

    // launch order puts the fused GEMM at the ncu-profiled index 3
    round_Ah<<<8192, 256>>>(hidden, a2p);                                     // 0 (FIXED grid)
    round_Bh<<<12288, 256>>>(w_qkv, wF, 6144, 8192, 0);                       // 1
    round_Bh<<<4096, 256>>>(w_g,    wF, 2048, 8192, 6144);                    // 2
    // 3) fused QKV+gate projection (pure fp16, K=2048)  <-- profiled
    gemm_fp16<<<dim3(64, 32), 128, GSM>>>(a2p, wF, qkvp, gatep, 4096, QKVW, NHD, 8192);
    chunk_stats_kernel<<<B_ * NH_ * NC_, 256, SMEM3>>>(qnw, knw, positions);  // 4
    scan_kernel<<<2048, 256>>>(rec);                                          // 5
    o_inter_kernel<<<B_ * NH_ * NC_, 256, SMEM6>>>(positions);                // 6
    round_Bh<<<4096, 256>>>(w_dense, wD, 2048, 2048, 0);                      // 7
    gating_split_kernel<<<B_ * S_, 256>>>(gnw, a2p);                          // 8
    // 9) dense projection -> d_out
    gemm_fp16<<<dim3(16, 32), 128, GSM>>>(a2p, wD, out, nullptr, 4096, NHD, 0, 2048);
}